// round 2
// baseline (speedup 1.0000x reference)
#include <cuda_runtime.h>
#include <cuda_bf16.h>
#include <cstdint>
#include <cstddef>

// ============================================================================
// EnhancedGNNEncoder: 2x GCNConv(+BN+ReLU) + GCNConv mu / GCNConv logstd
//   N=100000 nodes, E=3200000 edges, dims 81 -> 64 -> 64 -> {32,32}
// Strategy:
//   - Build CSR (grouped by dst) once per launch: degree -> scan -> fill.
//   - dis[i] = rsqrt(in_deg[i]+1); norm(s,d) = dis[s]*dis[d]; self loop fused.
//   - 3 GEMMs (fp32, smem-tiled); BN+ReLU fused into GEMM input load.
//   - 3 aggregation passes, one warp per node, no float atomics.
//   - mu/logstd share one pass via concatenated [Wmu|Wls].
// ============================================================================

#define MAXN 100000
#define MAXE 3200000

__device__ int   g_deg[MAXN];
__device__ int   g_rowptr[MAXN];
__device__ int   g_next[MAXN];
__device__ int   g_srcs[MAXE];
__device__ float g_dis[MAXN];
__device__ float g_A[(size_t)MAXN * 64];
__device__ float g_B[(size_t)MAXN * 64];
__device__ float g_stats[2 * 128];     // per BN layer: [sum(64), sumsq(64)]
__device__ float g_bnscale[2 * 64];
__device__ float g_bnshift[2 * 64];
__device__ int   g_blocksum[1024];
__device__ int   g_is64;

// ---------------------------------------------------------------------------
// dtype probe: int64 edge_index has zero high words; int32 essentially never
// has 2048 consecutive odd-position zeros (values uniform in [0,100000)).
// ---------------------------------------------------------------------------
__global__ void k_detect(const unsigned* __restrict__ p) {
    unsigned acc = 0;
    for (int k = threadIdx.x; k < 2048; k += 256) acc |= p[2 * k + 1];
#pragma unroll
    for (int off = 16; off; off >>= 1) acc |= __shfl_xor_sync(0xffffffffu, acc, off);
    __shared__ unsigned w[8];
    if ((threadIdx.x & 31) == 0) w[threadIdx.x >> 5] = acc;
    __syncthreads();
    if (threadIdx.x == 0) {
        unsigned t = 0;
#pragma unroll
        for (int i = 0; i < 8; i++) t |= w[i];
        g_is64 = (t == 0) ? 1 : 0;
    }
}

__global__ void k_init(int n) {
    int i = blockIdx.x * blockDim.x + threadIdx.x;
    if (i < n)   g_deg[i] = 0;
    if (i < 256) g_stats[i] = 0.f;
}

__device__ __forceinline__ int edge_dst(const void* ei, int e, int E, int is64) {
    if (is64) return (int)((const long long*)ei)[(long long)E + e];
    return ((const int*)ei)[E + e];
}
__device__ __forceinline__ int edge_src(const void* ei, int e, int E, int is64) {
    if (is64) return (int)((const long long*)ei)[e];
    return ((const int*)ei)[e];
}

__global__ void k_deg(const void* __restrict__ ei, int E) {
    int e = blockIdx.x * blockDim.x + threadIdx.x;
    if (e >= E) return;
    const int is64 = g_is64;
    int d = edge_dst(ei, e, E, is64);
    atomicAdd(&g_deg[d], 1);
}

// exclusive scan of g_deg -> g_rowptr (3 kernels, 1024-elem chunks)
__global__ void k_scan1(int n) {
    const int t = threadIdx.x;             // 256 threads, 4 elems each
    const int base = blockIdx.x * 1024;
    int i0 = base + t * 4;
    int v0 = (i0 + 0 < n) ? g_deg[i0 + 0] : 0;
    int v1 = (i0 + 1 < n) ? g_deg[i0 + 1] : 0;
    int v2 = (i0 + 2 < n) ? g_deg[i0 + 2] : 0;
    int v3 = (i0 + 3 < n) ? g_deg[i0 + 3] : 0;
    int tsum = v0 + v1 + v2 + v3;
    int lane = t & 31, w = t >> 5;
    int incl = tsum;
#pragma unroll
    for (int off = 1; off < 32; off <<= 1) {
        int x = __shfl_up_sync(0xffffffffu, incl, off);
        if (lane >= off) incl += x;
    }
    __shared__ int wsum[8];
    if (lane == 31) wsum[w] = incl;
    __syncthreads();
    if (t < 8) {
        int x = wsum[t];
        int s = x;
#pragma unroll
        for (int off = 1; off < 8; off <<= 1) {
            int y = __shfl_up_sync(0xffu, s, off);
            if (t >= off) s += y;
        }
        wsum[t] = s - x;   // exclusive
    }
    __syncthreads();
    int texcl = wsum[w] + incl - tsum;
    if (i0 + 0 < n) g_rowptr[i0 + 0] = texcl;
    if (i0 + 1 < n) g_rowptr[i0 + 1] = texcl + v0;
    if (i0 + 2 < n) g_rowptr[i0 + 2] = texcl + v0 + v1;
    if (i0 + 3 < n) g_rowptr[i0 + 3] = texcl + v0 + v1 + v2;
    if (t == 255) g_blocksum[blockIdx.x] = texcl + tsum;
}

__global__ void k_scan2(int nb) {  // 1 block, 128 threads; nb <= 128
    int t = threadIdx.x;
    __shared__ int sh[128];
    int v = (t < nb) ? g_blocksum[t] : 0;
    sh[t] = v;
    __syncthreads();
    for (int off = 1; off < 128; off <<= 1) {
        int x = (t >= off) ? sh[t - off] : 0;
        __syncthreads();
        sh[t] += x;
        __syncthreads();
    }
    if (t < nb) g_blocksum[t] = sh[t] - v;  // exclusive
}

__global__ void k_scan3(int n) {
    int i = blockIdx.x * blockDim.x + threadIdx.x;
    if (i >= n) return;
    int rp = g_rowptr[i] + g_blocksum[i >> 10];
    g_rowptr[i] = rp;
    g_next[i] = rp;
    g_dis[i] = rsqrtf((float)(g_deg[i] + 1));  // +1 self loop, always > 0
}

__global__ void k_fill(const void* __restrict__ ei, int E) {
    int e = blockIdx.x * blockDim.x + threadIdx.x;
    if (e >= E) return;
    const int is64 = g_is64;
    int s = edge_src(ei, e, E, is64);
    int d = edge_dst(ei, e, E, is64);
    int pos = atomicAdd(&g_next[d], 1);
    g_srcs[pos] = s;
}

// ---------------------------------------------------------------------------
// GEMM1: g_A = x[N,81] @ W1[81,64]   (no bias; bias applied post-aggregation)
// ---------------------------------------------------------------------------
__global__ void k_gemm81(const float* __restrict__ x, const float* __restrict__ W, int n) {
    __shared__ float Ws[81 * 64];
    __shared__ float Xs[64 * 81];
    const int t = threadIdx.x;           // 256
    const int r0 = blockIdx.x * 64;
    for (int i = t; i < 81 * 64; i += 256) Ws[i] = W[i];
    {
        size_t gbase = (size_t)r0 * 81;
        size_t lim = (size_t)n * 81;
        for (int i = t; i < 64 * 81; i += 256) {
            size_t g = gbase + i;
            Xs[i] = (g < lim) ? x[g] : 0.f;
        }
    }
    __syncthreads();
    const int row = t >> 2, cg = t & 3;
    float4 a0 = {0,0,0,0}, a1 = {0,0,0,0}, a2 = {0,0,0,0}, a3 = {0,0,0,0};
    const float* xr = &Xs[row * 81];
    for (int k = 0; k < 81; k++) {
        float xv = xr[k];
        const float4* w4 = (const float4*)&Ws[k * 64 + cg * 16];
        float4 w;
        w = w4[0]; a0.x += xv*w.x; a0.y += xv*w.y; a0.z += xv*w.z; a0.w += xv*w.w;
        w = w4[1]; a1.x += xv*w.x; a1.y += xv*w.y; a1.z += xv*w.z; a1.w += xv*w.w;
        w = w4[2]; a2.x += xv*w.x; a2.y += xv*w.y; a2.z += xv*w.z; a2.w += xv*w.w;
        w = w4[3]; a3.x += xv*w.x; a3.y += xv*w.y; a3.z += xv*w.z; a3.w += xv*w.w;
    }
    int gr = r0 + row;
    if (gr < n) {
        float4* o = (float4*)&g_A[(size_t)gr * 64 + cg * 16];
        o[0] = a0; o[1] = a1; o[2] = a2; o[3] = a3;
    }
}

// ---------------------------------------------------------------------------
// GEMM64: g_A = BNReLU(g_B)[N,64] @ W[64,64] ; W either dense or [Wa|Wb] concat
// ---------------------------------------------------------------------------
__global__ void k_gemm64(const float* __restrict__ Wa, const float* __restrict__ Wb,
                         int bnIdx, int n) {
    __shared__ float Ws[64 * 64];
    __shared__ float Xs[64 * 65];
    __shared__ float ssc[64], ssh[64];
    const int t = threadIdx.x;           // 256
    const int r0 = blockIdx.x * 64;
    if (t < 64) { ssc[t] = g_bnscale[bnIdx * 64 + t]; ssh[t] = g_bnshift[bnIdx * 64 + t]; }
    for (int i = t; i < 4096; i += 256) {
        int k = i >> 6, c = i & 63;
        float w;
        if (Wb) w = (c < 32) ? Wa[k * 32 + c] : Wb[k * 32 + (c - 32)];
        else    w = Wa[i];
        Ws[i] = w;
    }
    __syncthreads();
    for (int i = t; i < 4096; i += 256) {
        int lr = i >> 6, k = i & 63;
        int r = r0 + lr;
        float v = 0.f;
        if (r < n) {
            v = g_B[(size_t)r * 64 + k];
            v = fmaxf(fmaf(v, ssc[k], ssh[k]), 0.f);
        }
        Xs[lr * 65 + k] = v;
    }
    __syncthreads();
    const int row = t >> 2, cg = t & 3;
    float4 a0 = {0,0,0,0}, a1 = {0,0,0,0}, a2 = {0,0,0,0}, a3 = {0,0,0,0};
    const float* xr = &Xs[row * 65];
#pragma unroll 4
    for (int k = 0; k < 64; k++) {
        float xv = xr[k];
        const float4* w4 = (const float4*)&Ws[k * 64 + cg * 16];
        float4 w;
        w = w4[0]; a0.x += xv*w.x; a0.y += xv*w.y; a0.z += xv*w.z; a0.w += xv*w.w;
        w = w4[1]; a1.x += xv*w.x; a1.y += xv*w.y; a1.z += xv*w.z; a1.w += xv*w.w;
        w = w4[2]; a2.x += xv*w.x; a2.y += xv*w.y; a2.z += xv*w.z; a2.w += xv*w.w;
        w = w4[3]; a3.x += xv*w.x; a3.y += xv*w.y; a3.z += xv*w.z; a3.w += xv*w.w;
    }
    int gr = r0 + row;
    if (gr < n) {
        float4* o = (float4*)&g_A[(size_t)gr * 64 + cg * 16];
        o[0] = a0; o[1] = a1; o[2] = a2; o[3] = a3;
    }
}

// ---------------------------------------------------------------------------
// Aggregation: one warp per node. out[i] = dis[i]*(dis[i]*A[i] + sum_s dis[s]*A[s]) + bias
//   mode 0/1: out -> g_B, accumulate BN stats into g_stats[mode]
//   mode 2:   split: cols 0..31 + bias -> dout[i,:], cols 32..63 + bias2 -> dout[N..][i,:]
// ---------------------------------------------------------------------------
__global__ void k_agg(float* __restrict__ dout, const float* __restrict__ bias,
                      const float* __restrict__ bias2, int n, int mode) {
    const int wid = (blockIdx.x * blockDim.x + threadIdx.x) >> 5;
    const int lane = threadIdx.x & 31;
    __shared__ float ssum[64], ssq[64];
    if (mode < 2) {
        if (threadIdx.x < 64) { ssum[threadIdx.x] = 0.f; ssq[threadIdx.x] = 0.f; }
        __syncthreads();
    }
    float rx = 0.f, ry = 0.f;
    const bool active = (wid < n);
    if (active) {
        const int i = wid;
        const float di = g_dis[i];
        const float2* Af = (const float2*)g_A;
        float2 a = Af[(size_t)i * 32 + lane];
        float ax = di * a.x, ay = di * a.y;        // self loop contribution
        const int beg = g_rowptr[i];
        const int cnt = g_deg[i];
        int j = 0;
        while (j < cnt) {
            int m = cnt - j; if (m > 32) m = 32;
            int   myS = (lane < m) ? g_srcs[beg + j + lane] : 0;
            float myD = (lane < m) ? g_dis[myS] : 0.f;
            int q = 0;
            for (; q + 1 < m; q += 2) {
                int   s0 = __shfl_sync(0xffffffffu, myS, q);
                float d0 = __shfl_sync(0xffffffffu, myD, q);
                int   s1 = __shfl_sync(0xffffffffu, myS, q + 1);
                float d1 = __shfl_sync(0xffffffffu, myD, q + 1);
                float2 v0 = Af[(size_t)s0 * 32 + lane];
                float2 v1 = Af[(size_t)s1 * 32 + lane];
                ax += d0 * v0.x; ay += d0 * v0.y;
                ax += d1 * v1.x; ay += d1 * v1.y;
            }
            if (q < m) {
                int   s0 = __shfl_sync(0xffffffffu, myS, q);
                float d0 = __shfl_sync(0xffffffffu, myD, q);
                float2 v0 = Af[(size_t)s0 * 32 + lane];
                ax += d0 * v0.x; ay += d0 * v0.y;
            }
            j += m;
        }
        rx = di * ax; ry = di * ay;
        if (mode < 2) {
            float2 o = { rx + bias[2 * lane], ry + bias[2 * lane + 1] };
            ((float2*)g_B)[(size_t)i * 32 + lane] = o;
            rx = o.x; ry = o.y;   // stats on biased output (BN input)
        } else {
            if (lane < 16) {
                float2 o = { rx + bias[2 * lane], ry + bias[2 * lane + 1] };
                ((float2*)dout)[(size_t)i * 16 + lane] = o;
            } else {
                int l2 = lane - 16;
                float2 o = { rx + bias2[2 * l2], ry + bias2[2 * l2 + 1] };
                ((float2*)(dout + (size_t)n * 32))[(size_t)i * 16 + l2] = o;
            }
        }
    }
    if (mode < 2) {
        if (active) {
            atomicAdd(&ssum[2 * lane],     rx);
            atomicAdd(&ssum[2 * lane + 1], ry);
            atomicAdd(&ssq[2 * lane],      rx * rx);
            atomicAdd(&ssq[2 * lane + 1],  ry * ry);
        }
        __syncthreads();
        if (threadIdx.x < 64) {
            atomicAdd(&g_stats[mode * 128 + threadIdx.x],      ssum[threadIdx.x]);
            atomicAdd(&g_stats[mode * 128 + 64 + threadIdx.x], ssq[threadIdx.x]);
        }
    }
}

__global__ void k_bn(const float* __restrict__ g, const float* __restrict__ beta,
                     int idx, float invn) {
    int t = threadIdx.x;  // 64
    float sum = g_stats[idx * 128 + t];
    float sq  = g_stats[idx * 128 + 64 + t];
    float m   = sum * invn;
    float var = sq * invn - m * m;
    float sc  = g[t] * rsqrtf(var + 1e-5f);
    g_bnscale[idx * 64 + t] = sc;
    g_bnshift[idx * 64 + t] = beta[t] - m * sc;
}

// ---------------------------------------------------------------------------
extern "C" void kernel_launch(void* const* d_in, const int* in_sizes, int n_in,
                              void* d_out, int out_size) {
    const float* x     = (const float*)d_in[0];
    const void*  ei    = d_in[1];
    const float* W1    = (const float*)d_in[2];
    const float* b1    = (const float*)d_in[3];
    const float* g1    = (const float*)d_in[4];
    const float* beta1 = (const float*)d_in[5];
    const float* W2    = (const float*)d_in[6];
    const float* b2    = (const float*)d_in[7];
    const float* g2    = (const float*)d_in[8];
    const float* beta2 = (const float*)d_in[9];
    const float* Wmu   = (const float*)d_in[10];
    const float* bmu   = (const float*)d_in[11];
    const float* Wls   = (const float*)d_in[12];
    const float* bls   = (const float*)d_in[13];
    float* out = (float*)d_out;

    const int n = in_sizes[0] / 81;
    const int E = in_sizes[1] / 2;

    const int TB = 256;
    const int nBlkN  = (n + TB - 1) / TB;
    const int nBlkE  = (E + TB - 1) / TB;
    const int nbScan = (n + 1023) / 1024;
    const int nBlkG  = (n + 63) / 64;       // GEMM blocks (64 rows each)
    const int nBlkW  = (n * 32 + TB - 1) / TB;  // agg: 1 warp/node

    // Graph build
    k_detect<<<1, 256>>>((const unsigned*)ei);
    k_init<<<nBlkN, TB>>>(n);
    k_deg<<<nBlkE, TB>>>(ei, E);
    k_scan1<<<nbScan, 256>>>(n);
    k_scan2<<<1, 128>>>(nbScan);
    k_scan3<<<nBlkN, TB>>>(n);
    k_fill<<<nBlkE, TB>>>(ei, E);

    // Layer 1
    k_gemm81<<<nBlkG, 256>>>(x, W1, n);
    k_agg<<<nBlkW, TB>>>(nullptr, b1, nullptr, n, 0);
    k_bn<<<1, 64>>>(g1, beta1, 0, 1.0f / (float)n);

    // Layer 2
    k_gemm64<<<nBlkG, 256>>>(W2, nullptr, 0, n);
    k_agg<<<nBlkW, TB>>>(nullptr, b2, nullptr, n, 1);
    k_bn<<<1, 64>>>(g2, beta2, 1, 1.0f / (float)n);

    // mu / logstd (fused via concat weights)
    k_gemm64<<<nBlkG, 256>>>(Wmu, Wls, 1, n);
    k_agg<<<nBlkW, TB>>>(out, bmu, bls, n, 2);
}

// round 3
// speedup vs baseline: 1.6047x; 1.6047x over previous
#include <cuda_runtime.h>
#include <cuda_bf16.h>
#include <cstdint>
#include <cstddef>

// ============================================================================
// EnhancedGNNEncoder: 2x GCNConv(+BN+ReLU) + GCNConv mu / GCNConv logstd
//   N=100000, E=3200000, dims 81 -> 64 -> 64 -> {32|32}
// R3 changes vs R2 (674us):
//   - GEMM epilogue pre-scales rows by dis[row]; agg gathers need no dis[s],
//     no per-neighbor multiply, and the self-loop row is just Ascaled[i].
//   - Agg: half-warp float4 gather, 2 neighbors/iter, 1 shfl.idx/iter,
//     butterfly-combine at the end. ~3x fewer warp instructions per edge.
//   - GEMMs: 4x4 register tiling (2x LDS.128 per k per thread), BN scale/shift
//     computed inline in the GEMM prologue (k_bn launches removed).
// ============================================================================

#define MAXN 100000
#define MAXE 3200000

__device__ int   g_deg[MAXN];
__device__ int   g_rowptr[MAXN];
__device__ int   g_next[MAXN];
__device__ int   g_srcs[MAXE];
__device__ float g_dis[MAXN];
__device__ float g_A[(size_t)MAXN * 64];   // dis-prescaled GEMM outputs
__device__ float g_B[(size_t)MAXN * 64];   // aggregation outputs (BN inputs)
__device__ float g_stats[2 * 128];         // per BN layer: sum(64) | sumsq(64)
__device__ int   g_blocksum[1024];
__device__ int   g_is64;

// ---------------------------------------------------------------------------
// dtype probe: int64 edge_index has zero high words.
// ---------------------------------------------------------------------------
__global__ void k_detect(const unsigned* __restrict__ p) {
    unsigned acc = 0;
    for (int k = threadIdx.x; k < 2048; k += 256) acc |= p[2 * k + 1];
#pragma unroll
    for (int off = 16; off; off >>= 1) acc |= __shfl_xor_sync(0xffffffffu, acc, off);
    __shared__ unsigned w[8];
    if ((threadIdx.x & 31) == 0) w[threadIdx.x >> 5] = acc;
    __syncthreads();
    if (threadIdx.x == 0) {
        unsigned t = 0;
#pragma unroll
        for (int i = 0; i < 8; i++) t |= w[i];
        g_is64 = (t == 0) ? 1 : 0;
    }
}

__global__ void k_init(int n) {
    int i = blockIdx.x * blockDim.x + threadIdx.x;
    if (i < n)   g_deg[i] = 0;
    if (i < 256) g_stats[i] = 0.f;
}

__device__ __forceinline__ int edge_dst(const void* ei, int e, int E, int is64) {
    if (is64) return (int)((const long long*)ei)[(long long)E + e];
    return ((const int*)ei)[E + e];
}
__device__ __forceinline__ int edge_src(const void* ei, int e, int E, int is64) {
    if (is64) return (int)((const long long*)ei)[e];
    return ((const int*)ei)[e];
}

__global__ void k_deg(const void* __restrict__ ei, int E) {
    int e = blockIdx.x * blockDim.x + threadIdx.x;
    if (e >= E) return;
    atomicAdd(&g_deg[edge_dst(ei, e, E, g_is64)], 1);
}

__global__ void k_scan1(int n) {
    const int t = threadIdx.x;
    const int base = blockIdx.x * 1024;
    int i0 = base + t * 4;
    int v0 = (i0 + 0 < n) ? g_deg[i0 + 0] : 0;
    int v1 = (i0 + 1 < n) ? g_deg[i0 + 1] : 0;
    int v2 = (i0 + 2 < n) ? g_deg[i0 + 2] : 0;
    int v3 = (i0 + 3 < n) ? g_deg[i0 + 3] : 0;
    int tsum = v0 + v1 + v2 + v3;
    int lane = t & 31, w = t >> 5;
    int incl = tsum;
#pragma unroll
    for (int off = 1; off < 32; off <<= 1) {
        int x = __shfl_up_sync(0xffffffffu, incl, off);
        if (lane >= off) incl += x;
    }
    __shared__ int wsum[8];
    if (lane == 31) wsum[w] = incl;
    __syncthreads();
    if (t < 8) {
        int x = wsum[t];
        int s = x;
#pragma unroll
        for (int off = 1; off < 8; off <<= 1) {
            int y = __shfl_up_sync(0xffu, s, off);
            if (t >= off) s += y;
        }
        wsum[t] = s - x;
    }
    __syncthreads();
    int texcl = wsum[w] + incl - tsum;
    if (i0 + 0 < n) g_rowptr[i0 + 0] = texcl;
    if (i0 + 1 < n) g_rowptr[i0 + 1] = texcl + v0;
    if (i0 + 2 < n) g_rowptr[i0 + 2] = texcl + v0 + v1;
    if (i0 + 3 < n) g_rowptr[i0 + 3] = texcl + v0 + v1 + v2;
    if (t == 255) g_blocksum[blockIdx.x] = texcl + tsum;
}

__global__ void k_scan2(int nb) {
    int t = threadIdx.x;
    __shared__ int sh[128];
    int v = (t < nb) ? g_blocksum[t] : 0;
    sh[t] = v;
    __syncthreads();
    for (int off = 1; off < 128; off <<= 1) {
        int x = (t >= off) ? sh[t - off] : 0;
        __syncthreads();
        sh[t] += x;
        __syncthreads();
    }
    if (t < nb) g_blocksum[t] = sh[t] - v;
}

__global__ void k_scan3(int n) {
    int i = blockIdx.x * blockDim.x + threadIdx.x;
    if (i >= n) return;
    int rp = g_rowptr[i] + g_blocksum[i >> 10];
    g_rowptr[i] = rp;
    g_next[i] = rp;
    g_dis[i] = rsqrtf((float)(g_deg[i] + 1));
}

__global__ void k_fill(const void* __restrict__ ei, int E) {
    int e = blockIdx.x * blockDim.x + threadIdx.x;
    if (e >= E) return;
    const int is64 = g_is64;
    int s = edge_src(ei, e, E, is64);
    int d = edge_dst(ei, e, E, is64);
    int pos = atomicAdd(&g_next[d], 1);
    g_srcs[pos] = s;
}

// ---------------------------------------------------------------------------
// GEMM1: g_A[r] = dis[r] * (x[r,81] @ W1[81,64]). 4x4 register tiling.
// ---------------------------------------------------------------------------
__global__ void k_gemm81(const float* __restrict__ x, const float* __restrict__ W, int n) {
    __shared__ float Ws[81 * 64];
    __shared__ float Xs[81 * 68];   // [k][row], stride 68 (16B-aligned rows)
    __shared__ float ds[64];
    const int t = threadIdx.x;          // 256
    const int r0b = blockIdx.x * 64;
    for (int i = t; i < 81 * 64; i += 256) Ws[i] = W[i];
    if (t < 64) { int r = r0b + t; ds[t] = (r < n) ? g_dis[r] : 0.f; }
    {
        size_t gbase = (size_t)r0b * 81;
        size_t lim = (size_t)n * 81;
        for (int i = t; i < 64 * 81; i += 256) {
            size_t g = gbase + i;
            float v = (g < lim) ? x[g] : 0.f;
            int row = i / 81, k = i - row * 81;
            Xs[k * 68 + row] = v;
        }
    }
    __syncthreads();
    const int lr = (t >> 4) * 4;        // local row base
    const int c0 = (t & 15) * 4;        // col base
    float4 a0 = {0,0,0,0}, a1 = {0,0,0,0}, a2 = {0,0,0,0}, a3 = {0,0,0,0};
#pragma unroll 3
    for (int k = 0; k < 81; k++) {
        float4 xv = *(const float4*)&Xs[k * 68 + lr];
        float4 wv = *(const float4*)&Ws[k * 64 + c0];
        a0.x += xv.x * wv.x; a0.y += xv.x * wv.y; a0.z += xv.x * wv.z; a0.w += xv.x * wv.w;
        a1.x += xv.y * wv.x; a1.y += xv.y * wv.y; a1.z += xv.y * wv.z; a1.w += xv.y * wv.w;
        a2.x += xv.z * wv.x; a2.y += xv.z * wv.y; a2.z += xv.z * wv.z; a2.w += xv.z * wv.w;
        a3.x += xv.w * wv.x; a3.y += xv.w * wv.y; a3.z += xv.w * wv.z; a3.w += xv.w * wv.w;
    }
    float4 accs[4] = {a0, a1, a2, a3};
#pragma unroll
    for (int j = 0; j < 4; j++) {
        int r = r0b + lr + j;
        if (r < n) {
            float d = ds[lr + j];
            float4 o = accs[j];
            o.x *= d; o.y *= d; o.z *= d; o.w *= d;
            *(float4*)&g_A[(size_t)r * 64 + c0] = o;
        }
    }
}

// ---------------------------------------------------------------------------
// GEMM64: g_A[r] = dis[r] * (BNReLU(g_B)[r,64] @ W[64,64])
//   BN scale/shift computed inline from g_stats[bnIdx]. W = Wa or [Wa|Wb].
// ---------------------------------------------------------------------------
__global__ void k_gemm64(const float* __restrict__ Wa, const float* __restrict__ Wb,
                         const float* __restrict__ gamma, const float* __restrict__ beta,
                         int bnIdx, int n, float invn) {
    __shared__ float Ws[64 * 64];
    __shared__ float Xs[64 * 68];   // [k][row]
    __shared__ float ssc[64], ssh[64], ds[64];
    const int t = threadIdx.x;          // 256
    const int r0b = blockIdx.x * 64;
    if (t < 64) {
        float sum = g_stats[bnIdx * 128 + t];
        float sq  = g_stats[bnIdx * 128 + 64 + t];
        float m   = sum * invn;
        float var = sq * invn - m * m;
        float sc  = gamma[t] * rsqrtf(var + 1e-5f);
        ssc[t] = sc;
        ssh[t] = beta[t] - m * sc;
        int r = r0b + t; ds[t] = (r < n) ? g_dis[r] : 0.f;
    }
    for (int i = t; i < 4096; i += 256) {
        int k = i >> 6, c = i & 63;
        Ws[i] = Wb ? ((c < 32) ? Wa[k * 32 + c] : Wb[k * 32 + (c - 32)]) : Wa[i];
    }
    __syncthreads();   // ssc/ssh ready before X staging uses them
    for (int i = t; i < 4096; i += 256) {
        int row = i >> 6, k = i & 63;
        int r = r0b + row;
        float v = 0.f;
        if (r < n) {
            v = g_B[(size_t)r * 64 + k];
            v = fmaxf(fmaf(v, ssc[k], ssh[k]), 0.f);
        }
        Xs[k * 68 + row] = v;
    }
    __syncthreads();
    const int lr = (t >> 4) * 4;
    const int c0 = (t & 15) * 4;
    float4 a0 = {0,0,0,0}, a1 = {0,0,0,0}, a2 = {0,0,0,0}, a3 = {0,0,0,0};
#pragma unroll 4
    for (int k = 0; k < 64; k++) {
        float4 xv = *(const float4*)&Xs[k * 68 + lr];
        float4 wv = *(const float4*)&Ws[k * 64 + c0];
        a0.x += xv.x * wv.x; a0.y += xv.x * wv.y; a0.z += xv.x * wv.z; a0.w += xv.x * wv.w;
        a1.x += xv.y * wv.x; a1.y += xv.y * wv.y; a1.z += xv.y * wv.z; a1.w += xv.y * wv.w;
        a2.x += xv.z * wv.x; a2.y += xv.z * wv.y; a2.z += xv.z * wv.z; a2.w += xv.z * wv.w;
        a3.x += xv.w * wv.x; a3.y += xv.w * wv.y; a3.z += xv.w * wv.z; a3.w += xv.w * wv.w;
    }
    float4 accs[4] = {a0, a1, a2, a3};
#pragma unroll
    for (int j = 0; j < 4; j++) {
        int r = r0b + lr + j;
        if (r < n) {
            float d = ds[lr + j];
            float4 o = accs[j];
            o.x *= d; o.y *= d; o.z *= d; o.w *= d;
            *(float4*)&g_A[(size_t)r * 64 + c0] = o;
        }
    }
}

// ---------------------------------------------------------------------------
// Aggregation: one warp per node, half-warp float4 gather, 2 neighbors/iter.
//   out[i] = dis[i] * (Ascaled[i] + sum_{s in N(i)} Ascaled[s]) + bias
//   mode 0/1 -> g_B + BN stats; mode 2 -> split mu | logstd to dout.
// ---------------------------------------------------------------------------
__global__ void k_agg(float* __restrict__ dout, const float* __restrict__ bias,
                      const float* __restrict__ bias2, int n, int mode) {
    const int w    = (blockIdx.x * blockDim.x + threadIdx.x) >> 5;
    const int lane = threadIdx.x & 31;
    const int hb   = lane >> 4;          // half-warp index (neighbor parity)
    const int cg   = lane & 15;          // float4 column group
    __shared__ float ssum[64], ssq[64];
    if (mode < 2) {
        if (threadIdx.x < 64) { ssum[threadIdx.x] = 0.f; ssq[threadIdx.x] = 0.f; }
        __syncthreads();
    }
    float4 acc = {0.f, 0.f, 0.f, 0.f};
    const bool active = (w < n);
    if (active) {
        const int beg = g_rowptr[w];
        const int cnt = g_deg[w];
        const float4* Af = (const float4*)g_A;
        int j = 0;
        while (j < cnt) {
            int m = cnt - j; if (m > 32) m = 32;
            int myS = (lane < m) ? g_srcs[beg + j + lane] : 0;
#pragma unroll 4
            for (int p = 0; p < 16; p++) {
                if (2 * p >= m) break;
                int idx = 2 * p + hb;
                int s = __shfl_sync(0xffffffffu, myS, idx);
                if (idx < m) {
                    float4 v = Af[(size_t)s * 16 + cg];
                    acc.x += v.x; acc.y += v.y; acc.z += v.z; acc.w += v.w;
                }
            }
            j += m;
        }
    }
    // combine even/odd halves (lanes l and l+16 hold same columns)
    acc.x += __shfl_xor_sync(0xffffffffu, acc.x, 16);
    acc.y += __shfl_xor_sync(0xffffffffu, acc.y, 16);
    acc.z += __shfl_xor_sync(0xffffffffu, acc.z, 16);
    acc.w += __shfl_xor_sync(0xffffffffu, acc.w, 16);

    if (active && hb == 0) {
        const float di = g_dis[w];
        float4 self = ((const float4*)g_A)[(size_t)w * 16 + cg];
        float4 o;
        o.x = di * (acc.x + self.x);
        o.y = di * (acc.y + self.y);
        o.z = di * (acc.z + self.z);
        o.w = di * (acc.w + self.w);
        if (mode < 2) {
            float4 b = ((const float4*)bias)[cg];
            o.x += b.x; o.y += b.y; o.z += b.z; o.w += b.w;
            ((float4*)g_B)[(size_t)w * 16 + cg] = o;
            int c = cg * 4;
            atomicAdd(&ssum[c + 0], o.x); atomicAdd(&ssq[c + 0], o.x * o.x);
            atomicAdd(&ssum[c + 1], o.y); atomicAdd(&ssq[c + 1], o.y * o.y);
            atomicAdd(&ssum[c + 2], o.z); atomicAdd(&ssq[c + 2], o.z * o.z);
            atomicAdd(&ssum[c + 3], o.w); atomicAdd(&ssq[c + 3], o.w * o.w);
        } else {
            if (cg < 8) {      // columns 0..31 -> mu
                float4 b = ((const float4*)bias)[cg];
                o.x += b.x; o.y += b.y; o.z += b.z; o.w += b.w;
                ((float4*)dout)[(size_t)w * 8 + cg] = o;
            } else {           // columns 32..63 -> logstd
                float4 b = ((const float4*)bias2)[cg - 8];
                o.x += b.x; o.y += b.y; o.z += b.z; o.w += b.w;
                ((float4*)(dout + (size_t)n * 32))[(size_t)w * 8 + (cg - 8)] = o;
            }
        }
    }
    if (mode < 2) {
        __syncthreads();
        if (threadIdx.x < 64) {
            atomicAdd(&g_stats[mode * 128 + threadIdx.x],      ssum[threadIdx.x]);
            atomicAdd(&g_stats[mode * 128 + 64 + threadIdx.x], ssq[threadIdx.x]);
        }
    }
}

// ---------------------------------------------------------------------------
extern "C" void kernel_launch(void* const* d_in, const int* in_sizes, int n_in,
                              void* d_out, int out_size) {
    const float* x     = (const float*)d_in[0];
    const void*  ei    = d_in[1];
    const float* W1    = (const float*)d_in[2];
    const float* b1    = (const float*)d_in[3];
    const float* g1    = (const float*)d_in[4];
    const float* beta1 = (const float*)d_in[5];
    const float* W2    = (const float*)d_in[6];
    const float* b2    = (const float*)d_in[7];
    const float* g2    = (const float*)d_in[8];
    const float* beta2 = (const float*)d_in[9];
    const float* Wmu   = (const float*)d_in[10];
    const float* bmu   = (const float*)d_in[11];
    const float* Wls   = (const float*)d_in[12];
    const float* bls   = (const float*)d_in[13];
    float* out = (float*)d_out;

    const int n = in_sizes[0] / 81;
    const int E = in_sizes[1] / 2;
    const float invn = 1.0f / (float)n;

    const int TB = 256;
    const int nBlkN  = (n + TB - 1) / TB;
    const int nBlkE  = (E + TB - 1) / TB;
    const int nbScan = (n + 1023) / 1024;
    const int nBlkG  = (n + 63) / 64;
    const int nBlkW  = (n + 7) / 8;      // agg: 1 warp/node, 8 warps/block

    // Graph build
    k_detect<<<1, 256>>>((const unsigned*)ei);
    k_init<<<nBlkN, TB>>>(n);
    k_deg<<<nBlkE, TB>>>(ei, E);
    k_scan1<<<nbScan, 256>>>(n);
    k_scan2<<<1, 128>>>(nbScan);
    k_scan3<<<nBlkN, TB>>>(n);
    k_fill<<<nBlkE, TB>>>(ei, E);

    // Layer 1
    k_gemm81<<<nBlkG, 256>>>(x, W1, n);
    k_agg<<<nBlkW, TB>>>(nullptr, b1, nullptr, n, 0);

    // Layer 2
    k_gemm64<<<nBlkG, 256>>>(W2, nullptr, g1, beta1, 0, n, invn);
    k_agg<<<nBlkW, TB>>>(nullptr, b2, nullptr, n, 1);

    // mu / logstd (fused concat weights)
    k_gemm64<<<nBlkG, 256>>>(Wmu, Wls, g2, beta2, 1, n, invn);
    k_agg<<<nBlkW, TB>>>(out, bmu, bls, n, 2);
}